// round 16
// baseline (speedup 1.0000x reference)
#include <cuda_runtime.h>
#include <cuda_bf16.h>
#include <stdint.h>
#include <math.h>

#define B_  64
#define T_  512
#define E_  512
#define H_  256
#define NT_ 20
#define HBUF (16 * 264 * 2)   /* bytes per h buffer */
#define NGEMM 80              /* gemm worker CTAs in fused kernel */

// ---------------- scratch (device globals) ------------------------------------
__device__ __nv_bfloat16 g_xbfA[B_ * T_ * E_];        // 32 MB  layer-0 input (bf16)
__device__ __nv_bfloat16 g_xbfB[B_ * T_ * E_];        // 32 MB  layer-1 input (bf16)
__device__ float g_xA[B_ * T_ * E_];                  // 64 MB  final layer output (fp32)
__device__ float g_xg[(size_t)B_ * T_ * 2048];        // 256 MB xg, POS-MAJOR [pos][b][2048]
__device__ __nv_bfloat16 g_wbf[2 * 2048 * E_];        // 4 MB   w_ih in bf16
__device__ unsigned g_flg[2][256];                    // per-layer pos-tile flags
__device__ float g_em[B_ * T_ * NT_];
__device__ float g_llh[B_];

// ---------------- small helpers ------------------------------------------------
__device__ __forceinline__ unsigned pack_bf2(float a, float b) {
    __nv_bfloat162 h2 = __floats2bfloat162_rn(a, b);
    return *reinterpret_cast<unsigned*>(&h2);
}
__device__ __forceinline__ void ldsm4(unsigned& a0, unsigned& a1, unsigned& a2, unsigned& a3,
                                      unsigned addr) {
    asm volatile("ldmatrix.sync.aligned.m8n8.x4.shared.b16 {%0,%1,%2,%3}, [%4];\n"
                 : "=r"(a0), "=r"(a1), "=r"(a2), "=r"(a3) : "r"(addr));
}
__device__ __forceinline__ void mma_bf(float& d0, float& d1, float& d2, float& d3,
                                       unsigned a0, unsigned a1, unsigned a2, unsigned a3,
                                       unsigned b0, unsigned b1) {
    asm volatile("mma.sync.aligned.m16n8k16.row.col.f32.bf16.bf16.f32 "
                 "{%0,%1,%2,%3},{%4,%5,%6,%7},{%8,%9},{%0,%1,%2,%3};\n"
                 : "+f"(d0), "+f"(d1), "+f"(d2), "+f"(d3)
                 : "r"(a0), "r"(a1), "r"(a2), "r"(a3), "r"(b0), "r"(b1));
}
__device__ __forceinline__ unsigned mapa_u32(unsigned addr, int rank) {
    unsigned out;
    asm("mapa.shared::cluster.u32 %0, %1, %2;" : "=r"(out) : "r"(addr), "r"(rank));
    return out;
}
__device__ __forceinline__ void st_dsm64(unsigned addr, unsigned long long v) {
    asm volatile("st.shared::cluster.b64 [%0], %1;" :: "r"(addr), "l"(v) : "memory");
}
__device__ __forceinline__ unsigned ld_acq(const unsigned* p) {
    unsigned v;
    asm volatile("ld.acquire.gpu.global.u32 %0, [%1];" : "=r"(v) : "l"(p) : "memory");
    return v;
}
__device__ __forceinline__ void red_rel_add1(unsigned* p) {
    asm volatile("red.release.gpu.global.add.u32 [%0], 1;" :: "l"(p) : "memory");
}
__device__ __forceinline__ float tanhfast(float x) {
    float y;
    asm("tanh.approx.f32 %0, %1;" : "=f"(y) : "f"(x));
    return y;
}
__device__ __forceinline__ float sigm(float x) { return 0.5f * tanhfast(0.5f * x) + 0.5f; }

// ---------------- prep kernels --------------------------------------------------
__global__ void k_pre() {              // zero both layers' tile flags each replay
    ((unsigned*)g_flg)[threadIdx.x] = 0u;   // 512 words
}
__global__ void k_wcvt(const float* __restrict__ w_ih, int half) {
    int i = ((half * 1024 + blockIdx.x) * 256 + threadIdx.x) * 4;
    float4 v = *(const float4*)(w_ih + i);
    uint2 o;
    o.x = pack_bf2(v.x, v.y);
    o.y = pack_bf2(v.z, v.w);
    *(uint2*)(g_wbf + i) = o;
}
__global__ void k_gather(const int* __restrict__ ids, const float* __restrict__ embed) {
    int bt = blockIdx.x;
    int id = ids[bt];
    int e = threadIdx.x * 4;
    float4 v = *(const float4*)(embed + (size_t)id * E_ + e);
    uint2 o;
    o.x = pack_bf2(v.x, v.y);
    o.y = pack_bf2(v.z, v.w);
    *(uint2*)(g_xbfA + (size_t)bt * E_ + e) = o;
}

// ---------------- fused per-layer kernel: GEMM workers + LSTM clusters ---------
// grid = 144 CTAs (cluster 8): CTAs 0..63 = lstm (8 clusters), 64..143 = gemm.
// GEMM: xg[pos][b][:] = X @ W^T + bias, tiled 128x128 in pos-major M; tiles
// processed in earliest-demand order; per pos-tile flag = 16 ntile completions.
// LSTM: round-8 best config; prefetch gated on pos-tile flags (ld.acquire).
__global__ void __launch_bounds__(256, 1) __cluster_dims__(8, 1, 1)
k_layer(const float* __restrict__ w_hh, const int* __restrict__ lengths,
        const float* __restrict__ b_ih, const float* __restrict__ b_hh,
        int layer, int out_fp32) {
    __shared__ __align__(16) __nv_bfloat16 As[128 * 40];
    __shared__ __align__(16) __nv_bfloat16 Bs[128 * 40];
    __shared__ int s_pr[256];
    __shared__ int s_inv[256];
    __shared__ __align__(16) __nv_bfloat16 h_shD[2][16 * 264];
    __shared__ __align__(16) unsigned long long h_own[8][16];
    __shared__ int len_sh[16];

    int cta = blockIdx.x;
    int tid = threadIdx.x;
    int w = tid >> 5, lane = tid & 31;
    unsigned* flg = g_flg[layer];

    if (cta >= 64) {
        // ================= GEMM worker path =================
        int cg = cta - 64;
        const __nv_bfloat16* Xbf = layer ? g_xbfB : g_xbfA;
        const __nv_bfloat16* Wbf = g_wbf + (size_t)layer * 2048 * E_;
        const float* bi = b_ih + layer * 2048;
        const float* bh = b_hh + layer * 2048;

        // earliest-demand priority per pos-tile, then counting-rank
        if (tid < 256) {
            int pt = tid;
            int pr = 2 * pt;                       // fwd demand step
            for (int b2 = 0; b2 < 64; ++b2) {
                int len = lengths[b2];
                if (len - 1 >= 2 * pt) {           // bwd demand step
                    int d = len - 2 - 2 * pt;
                    if (d < 0) d = 0;
                    if (d < pr) pr = d;
                }
            }
            s_pr[pt] = pr;
        }
        __syncthreads();
        if (tid < 256) {
            int pt = tid, pr = s_pr[pt], rank = 0;
            for (int o = 0; o < 256; ++o) {
                int po = s_pr[o];
                if (po < pr || (po == pr && o < pt)) rank++;
            }
            s_inv[rank] = pt;
        }
        __syncthreads();

        unsigned a_base = (unsigned)__cvta_generic_to_shared(As);
        unsigned b_base = (unsigned)__cvta_generic_to_shared(Bs);
        int mbase = (w & 1) * 64, nbase = (w >> 1) * 32;
        int soff = (tid >> 2) * 40 + (tid & 3) * 8;

        for (int slot = cg; slot < 4096; slot += NGEMM) {
            int pt = s_inv[slot >> 4];
            int nt = slot & 15;
            int n0 = nt * 128;
            // pos-major row: m = pos*64 + b ; tile rows = pos {2pt,2pt+1} x b
            int grow = pt * 128 + (tid >> 2);
            int gb2 = grow & 63, gpos = grow >> 6;   // gpos == 2*pt for all threads
            const __nv_bfloat16* Ag = Xbf + ((size_t)gb2 * T_ + gpos) * E_ + (tid & 3) * 8;
            const __nv_bfloat16* Bg = Wbf + (size_t)(n0 + (tid >> 2)) * E_ + (tid & 3) * 8;

            float acc[4][4][4];
#pragma unroll
            for (int i = 0; i < 4; i++)
#pragma unroll
                for (int j = 0; j < 4; j++)
#pragma unroll
                    for (int r2 = 0; r2 < 4; r2++) acc[i][j][r2] = 0.f;

            uint4 ra[2], rb[2];
#pragma unroll
            for (int i = 0; i < 2; i++) {
                ra[i] = *(const uint4*)(Ag + i * E_);        // +1 pos
                rb[i] = *(const uint4*)(Bg + i * 64 * E_);
            }
            for (int kb = 0; kb < 16; ++kb) {
#pragma unroll
                for (int i = 0; i < 2; i++) {
                    *(uint4*)&As[soff + i * 64 * 40] = ra[i];
                    *(uint4*)&Bs[soff + i * 64 * 40] = rb[i];
                }
                __syncthreads();
                if (kb < 15) {
#pragma unroll
                    for (int i = 0; i < 2; i++) {
                        ra[i] = *(const uint4*)(Ag + (kb + 1) * 32 + i * E_);
                        rb[i] = *(const uint4*)(Bg + (kb + 1) * 32 + i * 64 * E_);
                    }
                }
#pragma unroll
                for (int kk = 0; kk < 32; kk += 16) {
                    unsigned aF[4][4], bF[4][2];
#pragma unroll
                    for (int mt = 0; mt < 4; ++mt) {
                        int row = mbase + mt * 16 + (lane & 15);
                        int col = kk + ((lane >> 4) << 3);
                        ldsm4(aF[mt][0], aF[mt][1], aF[mt][2], aF[mt][3],
                              a_base + (unsigned)(row * 40 + col) * 2);
                    }
#pragma unroll
                    for (int p = 0; p < 2; ++p) {
                        int row = nbase + 16 * p + ((lane >> 4) << 3) + (lane & 7);
                        int colb = kk + (((lane >> 3) & 1) << 3);
                        ldsm4(bF[2 * p][0], bF[2 * p][1], bF[2 * p + 1][0], bF[2 * p + 1][1],
                              b_base + (unsigned)(row * 40 + colb) * 2);
                    }
#pragma unroll
                    for (int mt = 0; mt < 4; ++mt)
#pragma unroll
                        for (int nt2 = 0; nt2 < 4; ++nt2)
                            mma_bf(acc[mt][nt2][0], acc[mt][nt2][1], acc[mt][nt2][2], acc[mt][nt2][3],
                                   aF[mt][0], aF[mt][1], aF[mt][2], aF[mt][3],
                                   bF[nt2][0], bF[nt2][1]);
                }
                __syncthreads();
            }
#pragma unroll
            for (int nt2 = 0; nt2 < 4; ++nt2) {
                int coln = n0 + nbase + 8 * nt2 + 2 * (lane & 3);
                float bb0 = bi[coln] + bh[coln];
                float bb1 = bi[coln + 1] + bh[coln + 1];
#pragma unroll
                for (int mt = 0; mt < 4; ++mt) {
                    int row = pt * 128 + mbase + 16 * mt + (lane >> 2);
                    *(float2*)&g_xg[(size_t)row * 2048 + coln] =
                        make_float2(acc[mt][nt2][0] + bb0, acc[mt][nt2][1] + bb1);
                    *(float2*)&g_xg[(size_t)(row + 8) * 2048 + coln] =
                        make_float2(acc[mt][nt2][2] + bb0, acc[mt][nt2][3] + bb1);
                }
            }
            __threadfence();
            __syncthreads();
            if (tid == 0) red_rel_add1(&flg[pt]);
            __syncthreads();
        }
        return;
    }

    // ================= LSTM path (round-8 config, gated pos-major xg) =========
    int ub  = cta & 7;
    int grp = cta >> 3;
    int bb  = grp & 3;
    int dir = grp >> 2;

    unsigned bfr[16][2][2];
    {
        int c2 = (lane & 3) * 2;
#pragma unroll
        for (int p = 0; p < 2; ++p) {
            int lc = 8 * p + (lane >> 2);
            int g = lc & 3, du2 = lc >> 2;
            const float* wr = w_hh +
                ((size_t)((layer * 2 + dir) * 1024 + g * 256 + ub * 32 + w * 4 + du2)) * 256;
#pragma unroll
            for (int kt = 0; kt < 16; ++kt) {
                bfr[kt][p][0] = pack_bf2(wr[kt * 16 + c2],     wr[kt * 16 + c2 + 1]);
                bfr[kt][p][1] = pack_bf2(wr[kt * 16 + c2 + 8], wr[kt * 16 + c2 + 9]);
            }
        }
    }
    if (tid < 16) len_sh[tid] = lengths[bb * 16 + tid];
    for (int i = tid; i < 16 * 264 / 2; i += 256)
        ((unsigned*)h_shD[0])[i] = 0u;
    __syncthreads();
    asm volatile("barrier.cluster.arrive.aligned;" ::: "memory");
    asm volatile("barrier.cluster.wait.aligned;" ::: "memory");

    int maxlen = 0;
#pragma unroll
    for (int i = 0; i < 16; i++) maxlen = max(maxlen, len_sh[i]);

    int q = lane & 3, r = lane >> 2;
    bool qe = (q & 1) == 0;
    int du = ((q & 1) << 1) | (q >> 1);
    int unit = ub * 32 + 4 * w + du;
    int len0 = len_sh[r], len1 = len_sh[r + 8];
    int gb0 = bb * 16 + r, gb1 = bb * 16 + r + 8;
    size_t off0 = (size_t)gb0 * 2048 + dir * 1024 + unit;   // pos-major xg offsets
    size_t off1 = (size_t)gb1 * 2048 + dir * 1024 + unit;

    unsigned hsh_base = (unsigned)__cvta_generic_to_shared(&h_shD[0][0]);
    unsigned a_addr0 = hsh_base + (unsigned)(lane & 15) * 528 + ((lane >> 4) << 4);
    int peer = lane & 7;
    unsigned dsm_peer = mapa_u32(hsh_base + (unsigned)((ub * 32 + 4 * w) * 2), peer);

    float cst0 = 0.f, cst1 = 0.f;
    float xa[2][8];
    int cf = -1, cb0 = -1, cb1 = -1;   // cached ready pos-tiles

#define WAIT_PT(pt, c) do { int _p = (pt); if (_p != (c)) { \
    while (ld_acq(&flg[_p]) < 16u) { __nanosleep(40); } (c) = _p; } } while (0)

    // gated prefetch for s = 0
    {
        int pos0 = dir ? (len0 - 1) : 0;
        int pos1 = dir ? (len1 - 1) : 0;
        if (dir == 0) { WAIT_PT(0, cf); }
        else { WAIT_PT(pos0 >> 1, cb0); WAIT_PT(pos1 >> 1, cb1); }
        const float* p0 = g_xg + (size_t)pos0 * 131072 + off0;
        const float* p1 = g_xg + (size_t)pos1 * 131072 + off1;
        xa[0][0] = p0[0]; xa[0][1] = p0[256]; xa[0][2] = p0[512]; xa[0][3] = p0[768];
        xa[0][4] = p1[0]; xa[0][5] = p1[256]; xa[0][6] = p1[512]; xa[0][7] = p1[768];
    }

    for (int s = 0; s < maxlen; ++s) {
        int p = s & 1;
        if (s + 1 < maxlen) {
            int sn = s + 1;
            if (dir == 0) { if (sn < len0 || sn < len1) WAIT_PT(sn >> 1, cf); }
            if (sn < len0) {
                int pos0 = dir ? (len0 - 1 - sn) : sn;
                if (dir) WAIT_PT(pos0 >> 1, cb0);
                const float* pp = g_xg + (size_t)pos0 * 131072 + off0;
                xa[p ^ 1][0] = pp[0]; xa[p ^ 1][1] = pp[256];
                xa[p ^ 1][2] = pp[512]; xa[p ^ 1][3] = pp[768];
            }
            if (sn < len1) {
                int pos1 = dir ? (len1 - 1 - sn) : sn;
                if (dir) WAIT_PT(pos1 >> 1, cb1);
                const float* pp = g_xg + (size_t)pos1 * 131072 + off1;
                xa[p ^ 1][4] = pp[0]; xa[p ^ 1][5] = pp[256];
                xa[p ^ 1][6] = pp[512]; xa[p ^ 1][7] = pp[768];
            }
        }

        if (s > 0)
            asm volatile("barrier.cluster.wait.aligned;" ::: "memory");

        unsigned a_addr = a_addr0 + (unsigned)p * HBUF;
        float aA[2][4], aB[2][4];
#pragma unroll
        for (int t = 0; t < 2; ++t)
#pragma unroll
            for (int i = 0; i < 4; ++i) { aA[t][i] = 0.f; aB[t][i] = 0.f; }
#pragma unroll
        for (int kt = 0; kt < 16; kt += 2) {
            unsigned A0, A1, A2, A3;
            ldsm4(A0, A1, A2, A3, a_addr + kt * 32);
            mma_bf(aA[0][0], aA[0][1], aA[0][2], aA[0][3],
                   A0, A1, A2, A3, bfr[kt][0][0], bfr[kt][0][1]);
            mma_bf(aA[1][0], aA[1][1], aA[1][2], aA[1][3],
                   A0, A1, A2, A3, bfr[kt][1][0], bfr[kt][1][1]);
            unsigned B0, B1, B2, B3;
            ldsm4(B0, B1, B2, B3, a_addr + (kt + 1) * 32);
            mma_bf(aB[0][0], aB[0][1], aB[0][2], aB[0][3],
                   B0, B1, B2, B3, bfr[kt + 1][0][0], bfr[kt + 1][0][1]);
            mma_bf(aB[1][0], aB[1][1], aB[1][2], aB[1][3],
                   B0, B1, B2, B3, bfr[kt + 1][1][0], bfr[kt + 1][1][1]);
        }
        float acc0[4], acc1[4];
#pragma unroll
        for (int i = 0; i < 4; ++i) { acc0[i] = aA[0][i] + aB[0][i];
                                      acc1[i] = aA[1][i] + aB[1][i]; }

        float own[4], rcv[4];
#pragma unroll
        for (int i = 0; i < 4; ++i) {
            float snd = qe ? acc1[i] : acc0[i];
            rcv[i] = __shfl_xor_sync(0xFFFFFFFFu, snd, 1);
            own[i] = qe ? acc0[i] : acc1[i];
        }
        float ai0 = (qe ? own[0] : rcv[0]) + xa[p][0];
        float af0 = (qe ? own[1] : rcv[1]) + xa[p][1];
        float ag0 = (qe ? rcv[0] : own[0]) + xa[p][2];
        float ao0 = (qe ? rcv[1] : own[1]) + xa[p][3];
        float ai1 = (qe ? own[2] : rcv[2]) + xa[p][4];
        float af1 = (qe ? own[3] : rcv[3]) + xa[p][5];
        float ag1 = (qe ? rcv[2] : own[2]) + xa[p][6];
        float ao1 = (qe ? rcv[3] : own[3]) + xa[p][7];

        bool v0 = s < len0, v1 = s < len1;
        float hv0 = 0.f, hv1 = 0.f;
        if (v0) {
            cst0 = sigm(af0) * cst0 + sigm(ai0) * tanhfast(ag0);
            hv0 = sigm(ao0) * tanhfast(cst0);
            ((__nv_bfloat16*)&h_own[w][r])[du] = __float2bfloat16(hv0);
        }
        if (v1) {
            cst1 = sigm(af1) * cst1 + sigm(ai1) * tanhfast(ag1);
            hv1 = sigm(ao1) * tanhfast(cst1);
            ((__nv_bfloat16*)&h_own[w][r + 8])[du] = __float2bfloat16(hv1);
        }
        __syncwarp();

        if (s + 1 < maxlen) {
            unsigned dbase = dsm_peer + (unsigned)(p ^ 1) * HBUF;
#pragma unroll
            for (int j = 0; j < 4; ++j) {
                int batch = (lane >> 3) + 4 * j;
                st_dsm64(dbase + (unsigned)batch * 528, h_own[w][batch]);
            }
            asm volatile("barrier.cluster.arrive.aligned;" ::: "memory");
        }

        if (v0) {
            int pos0 = dir ? (len0 - 1 - s) : s;
            size_t xoff = ((size_t)gb0 * T_ + pos0) * E_ + dir * H_ + unit;
            if (out_fp32) g_xA[xoff] = hv0; else g_xbfB[xoff] = __float2bfloat16(hv0);
        }
        if (v1) {
            int pos1 = dir ? (len1 - 1 - s) : s;
            size_t xoff = ((size_t)gb1 * T_ + pos1) * E_ + dir * H_ + unit;
            if (out_fp32) g_xA[xoff] = hv1; else g_xbfB[xoff] = __float2bfloat16(hv1);
        }
    }

    for (int t = len0; t < T_; ++t) {
        size_t xoff = ((size_t)gb0 * T_ + t) * E_ + dir * H_ + unit;
        if (out_fp32) g_xA[xoff] = 0.f; else g_xbfB[xoff] = __float2bfloat16(0.f);
    }
    for (int t = len1; t < T_; ++t) {
        size_t xoff = ((size_t)gb1 * T_ + t) * E_ + dir * H_ + unit;
        if (out_fp32) g_xA[xoff] = 0.f; else g_xbfB[xoff] = __float2bfloat16(0.f);
    }

    asm volatile("barrier.cluster.arrive.aligned;" ::: "memory");
    asm volatile("barrier.cluster.wait.aligned;" ::: "memory");
}

// ---------------- emissions -----------------------------------------------------
__global__ void k_emis(const float* __restrict__ fc_w, const float* __restrict__ fc_b) {
    int w = blockIdx.x * 8 + (threadIdx.x >> 5);
    int lane = threadIdx.x & 31;
    int j = lane < NT_ ? lane : 0;
    const float* x = g_xA + (size_t)w * E_;
    float acc = fc_b[j];
#pragma unroll 4
    for (int k = 0; k < E_; k += 4) {
        float4 xv = *(const float4*)(x + k);
        acc += xv.x * fc_w[(k + 0) * NT_ + j] + xv.y * fc_w[(k + 1) * NT_ + j]
             + xv.z * fc_w[(k + 2) * NT_ + j] + xv.w * fc_w[(k + 3) * NT_ + j];
    }
    if (lane < NT_) g_em[(size_t)w * NT_ + lane] = acc;
}

// ---------------- CRF -----------------------------------------------------------
__global__ void k_crf(const int* __restrict__ tags, const int* __restrict__ lengths,
                      const float* __restrict__ crf_start, const float* __restrict__ crf_end,
                      const float* __restrict__ crf_trans) {
    int b = blockIdx.x;
    int lane = threadIdx.x;
    int len = lengths[b];
    const int* tg = tags + b * T_;
    const float* em = g_em + (size_t)b * T_ * NT_;

    float part = 0.f;
    for (int t = lane; t < T_; t += 32) {
        if (t < len) {
            int tt = tg[t];
            part += em[t * NT_ + tt];
            if (t >= 1) part += crf_trans[tg[t - 1] * NT_ + tt];
        }
    }
#pragma unroll
    for (int o = 16; o; o >>= 1) part += __shfl_xor_sync(0xFFFFFFFFu, part, o);
    float numer = part + crf_start[tg[0]] + crf_end[tg[len - 1]];

    int j = lane < NT_ ? lane : 0;
    float etr[NT_];
#pragma unroll
    for (int i = 0; i < NT_; i++) etr[i] = expf(crf_trans[i * NT_ + j]);

    float s = crf_start[j] + em[j];
    for (int t = 1; t < len; ++t) {
        float sl = (lane < NT_) ? s : -1e30f;
        float m = sl;
#pragma unroll
        for (int o = 16; o; o >>= 1) m = fmaxf(m, __shfl_xor_sync(0xFFFFFFFFu, m, o));
        float es = expf(s - m);
        float z = 0.f;
#pragma unroll
        for (int i = 0; i < NT_; i++) {
            float ei = __shfl_sync(0xFFFFFFFFu, es, i);
            z += ei * etr[i];
        }
        s = m + logf(z) + em[t * NT_ + j];
    }
    s += crf_end[j];
    float sj = (lane < NT_) ? s : -1e30f;
    float mm = sj;
#pragma unroll
    for (int o = 16; o; o >>= 1) mm = fmaxf(mm, __shfl_xor_sync(0xFFFFFFFFu, mm, o));
    float zz = (lane < NT_) ? expf(sj - mm) : 0.f;
#pragma unroll
    for (int o = 16; o; o >>= 1) zz += __shfl_xor_sync(0xFFFFFFFFu, zz, o);
    float logZ = mm + logf(zz);
    if (lane == 0) g_llh[b] = numer - logZ;
}

// ---------------- final reduction ----------------------------------------------
__global__ void k_reduce(float* __restrict__ out) {
    int lane = threadIdx.x;
    float v = g_llh[lane];
    __shared__ float tmp[2];
#pragma unroll
    for (int o = 16; o; o >>= 1) v += __shfl_xor_sync(0xFFFFFFFFu, v, o);
    if ((lane & 31) == 0) tmp[lane >> 5] = v;
    __syncthreads();
    if (lane == 0) out[0] = -(tmp[0] + tmp[1]);
}

// ---------------- host launcher -------------------------------------------------
extern "C" void kernel_launch(void* const* d_in, const int* in_sizes, int n_in,
                              void* d_out, int out_size) {
    const int*   ids   = (const int*)d_in[0];
    const int*   lens  = (const int*)d_in[1];
    const int*   tags  = (const int*)d_in[2];
    const float* embed = (const float*)d_in[3];
    const float* w_ih  = (const float*)d_in[4];
    const float* w_hh  = (const float*)d_in[5];
    const float* b_ih  = (const float*)d_in[6];
    const float* b_hh  = (const float*)d_in[7];
    const float* fc_w  = (const float*)d_in[8];
    const float* fc_b  = (const float*)d_in[9];
    const float* c_st  = (const float*)d_in[10];
    const float* c_en  = (const float*)d_in[11];
    const float* c_tr  = (const float*)d_in[12];
    float* out = (float*)d_out;

    k_pre<<<1, 512>>>();                                       // 0
    k_wcvt<<<1024, 256>>>(w_ih, 0);                            // 1
    k_wcvt<<<1024, 256>>>(w_ih, 1);                            // 2
    k_gather<<<B_ * T_, 128>>>(ids, embed);                    // 3
    k_layer<<<144, 256>>>(w_hh, lens, b_ih, b_hh, 0, 0);       // 4
    k_layer<<<144, 256>>>(w_hh, lens, b_ih, b_hh, 1, 1);       // 5  <- profiled
    k_emis<<<B_ * T_ / 8, 256>>>(fc_w, fc_b);                  // 6
    k_crf<<<B_, 32>>>(tags, lens, c_st, c_en, c_tr);           // 7
    k_reduce<<<1, 64>>>(out);                                  // 8
}

// round 17
// speedup vs baseline: 2.0804x; 2.0804x over previous
#include <cuda_runtime.h>
#include <cuda_bf16.h>
#include <stdint.h>
#include <math.h>

#define B_  64
#define T_  512
#define E_  512
#define H_  256
#define NT_ 20
#define HBUF (16 * 264 * 2)   /* bytes per h buffer */

// ---------------- scratch (device globals) ------------------------------------
__device__ __nv_bfloat16 g_xbfA[B_ * T_ * E_];        // 32 MB  layer-0 input (bf16)
__device__ __nv_bfloat16 g_xbfB[B_ * T_ * E_];        // 32 MB  layer-1 input (bf16)
__device__ float g_xA[B_ * T_ * E_];                  // 64 MB  final layer output (fp32)
__device__ __nv_bfloat16 g_xg[(size_t)B_ * T_ * 2048];// 128 MB input projections (bf16)
__device__ __nv_bfloat16 g_wbf[2 * 2048 * E_];        // 4 MB   w_ih in bf16
__device__ float g_em[B_ * T_ * NT_];
__device__ float g_llh[B_];

// ---------------- small helpers ------------------------------------------------
__device__ __forceinline__ unsigned pack_bf2(float a, float b) {
    __nv_bfloat162 h2 = __floats2bfloat162_rn(a, b);
    return *reinterpret_cast<unsigned*>(&h2);
}
__device__ __forceinline__ void ldsm4(unsigned& a0, unsigned& a1, unsigned& a2, unsigned& a3,
                                      unsigned addr) {
    asm volatile("ldmatrix.sync.aligned.m8n8.x4.shared.b16 {%0,%1,%2,%3}, [%4];\n"
                 : "=r"(a0), "=r"(a1), "=r"(a2), "=r"(a3) : "r"(addr));
}
__device__ __forceinline__ void mma_bf(float& d0, float& d1, float& d2, float& d3,
                                       unsigned a0, unsigned a1, unsigned a2, unsigned a3,
                                       unsigned b0, unsigned b1) {
    asm volatile("mma.sync.aligned.m16n8k16.row.col.f32.bf16.bf16.f32 "
                 "{%0,%1,%2,%3},{%4,%5,%6,%7},{%8,%9},{%0,%1,%2,%3};\n"
                 : "+f"(d0), "+f"(d1), "+f"(d2), "+f"(d3)
                 : "r"(a0), "r"(a1), "r"(a2), "r"(a3), "r"(b0), "r"(b1));
}
__device__ __forceinline__ unsigned mapa_u32(unsigned addr, int rank) {
    unsigned out;
    asm("mapa.shared::cluster.u32 %0, %1, %2;" : "=r"(out) : "r"(addr), "r"(rank));
    return out;
}
__device__ __forceinline__ void st_dsm64(unsigned addr, unsigned long long v) {
    asm volatile("st.shared::cluster.b64 [%0], %1;" :: "r"(addr), "l"(v) : "memory");
}
__device__ __forceinline__ float tanhfast(float x) {
    float y;
    asm("tanh.approx.f32 %0, %1;" : "=f"(y) : "f"(x));
    return y;
}
__device__ __forceinline__ float sigm(float x) { return 0.5f * tanhfast(0.5f * x) + 0.5f; }

// ---------------- conversion / gather ------------------------------------------
__global__ void k_wcvt(const float* __restrict__ w_ih, int half) {
    int i = ((half * 1024 + blockIdx.x) * 256 + threadIdx.x) * 4;
    float4 v = *(const float4*)(w_ih + i);
    uint2 o;
    o.x = pack_bf2(v.x, v.y);
    o.y = pack_bf2(v.z, v.w);
    *(uint2*)(g_wbf + i) = o;
}

__global__ void k_gather(const int* __restrict__ ids, const float* __restrict__ embed) {
    int bt = blockIdx.x;
    int id = ids[bt];
    int e = threadIdx.x * 4;
    float4 v = *(const float4*)(embed + (size_t)id * E_ + e);
    uint2 o;
    o.x = pack_bf2(v.x, v.y);
    o.y = pack_bf2(v.z, v.w);
    *(uint2*)(g_xbfA + (size_t)bt * E_ + e) = o;
}

// ---------------- bf16 tensor-core GEMM: xg = X @ W^T + bias (bf16 out) --------
__global__ void __launch_bounds__(256) k_gemm_bf(const float* __restrict__ b_ih,
                                                 const float* __restrict__ b_hh,
                                                 int layer) {
    __shared__ __align__(16) __nv_bfloat16 As[128 * 40];
    __shared__ __align__(16) __nv_bfloat16 Bs[128 * 40];

    const __nv_bfloat16* Xbf = layer ? g_xbfB : g_xbfA;
    const __nv_bfloat16* Wbf = g_wbf + (size_t)layer * 2048 * E_;
    const float* bi = b_ih + layer * 2048;
    const float* bh = b_hh + layer * 2048;

    int m0 = blockIdx.y * 128, n0 = blockIdx.x * 128;
    int tid = threadIdx.x, w = tid >> 5, lane = tid & 31;

    const __nv_bfloat16* Ag = Xbf + (size_t)(m0 + (tid >> 2)) * E_ + (tid & 3) * 8;
    const __nv_bfloat16* Bg = Wbf + (size_t)(n0 + (tid >> 2)) * E_ + (tid & 3) * 8;
    int soff = (tid >> 2) * 40 + (tid & 3) * 8;

    unsigned a_base = (unsigned)__cvta_generic_to_shared(As);
    unsigned b_base = (unsigned)__cvta_generic_to_shared(Bs);

    int mbase = (w & 1) * 64, nbase = (w >> 1) * 32;

    float acc[4][4][4];
#pragma unroll
    for (int i = 0; i < 4; i++)
#pragma unroll
        for (int j = 0; j < 4; j++)
#pragma unroll
            for (int r = 0; r < 4; r++) acc[i][j][r] = 0.f;

    uint4 ra[2], rb[2];
#pragma unroll
    for (int i = 0; i < 2; i++) {
        ra[i] = *(const uint4*)(Ag + i * 64 * E_);
        rb[i] = *(const uint4*)(Bg + i * 64 * E_);
    }

    for (int kb = 0; kb < 16; ++kb) {
#pragma unroll
        for (int i = 0; i < 2; i++) {
            *(uint4*)&As[soff + i * 64 * 40] = ra[i];
            *(uint4*)&Bs[soff + i * 64 * 40] = rb[i];
        }
        __syncthreads();
        if (kb < 15) {
#pragma unroll
            for (int i = 0; i < 2; i++) {
                ra[i] = *(const uint4*)(Ag + (kb + 1) * 32 + i * 64 * E_);
                rb[i] = *(const uint4*)(Bg + (kb + 1) * 32 + i * 64 * E_);
            }
        }
#pragma unroll
        for (int kk = 0; kk < 32; kk += 16) {
            unsigned aF[4][4], bF[4][2];
#pragma unroll
            for (int mt = 0; mt < 4; ++mt) {
                int row = mbase + mt * 16 + (lane & 15);
                int col = kk + ((lane >> 4) << 3);
                ldsm4(aF[mt][0], aF[mt][1], aF[mt][2], aF[mt][3],
                      a_base + (unsigned)(row * 40 + col) * 2);
            }
#pragma unroll
            for (int p = 0; p < 2; ++p) {
                int row = nbase + 16 * p + ((lane >> 4) << 3) + (lane & 7);
                int colb = kk + (((lane >> 3) & 1) << 3);
                ldsm4(bF[2 * p][0], bF[2 * p][1], bF[2 * p + 1][0], bF[2 * p + 1][1],
                      b_base + (unsigned)(row * 40 + colb) * 2);
            }
#pragma unroll
            for (int mt = 0; mt < 4; ++mt)
#pragma unroll
                for (int nt = 0; nt < 4; ++nt)
                    mma_bf(acc[mt][nt][0], acc[mt][nt][1], acc[mt][nt][2], acc[mt][nt][3],
                           aF[mt][0], aF[mt][1], aF[mt][2], aF[mt][3],
                           bF[nt][0], bF[nt][1]);
        }
        __syncthreads();
    }

    // epilogue: add bias, pack to bf16, 4B stores
#pragma unroll
    for (int nt = 0; nt < 4; ++nt) {
        int coln = n0 + nbase + 8 * nt + 2 * (lane & 3);
        float bb0 = bi[coln] + bh[coln];
        float bb1 = bi[coln + 1] + bh[coln + 1];
#pragma unroll
        for (int mt = 0; mt < 4; ++mt) {
            int row = m0 + mbase + 16 * mt + (lane >> 2);
            *(unsigned*)&g_xg[(size_t)row * 2048 + coln] =
                pack_bf2(acc[mt][nt][0] + bb0, acc[mt][nt][1] + bb1);
            *(unsigned*)&g_xg[(size_t)(row + 8) * 2048 + coln] =
                pack_bf2(acc[mt][nt][2] + bb0, acc[mt][nt][3] + bb1);
        }
    }
}

// ---------------- persistent BiLSTM layer (round-8 best configuration) ---------
// 64 CTAs = 8 clusters of 8.  Cluster = (dir, batch-block of 16).
// CTA rank ub owns units [ub*32, ub*32+32); warp w owns units 4w..4w+3 with
// all four gates in its mma D-fragment.  Push + cluster.sync exchange.
__global__ void __launch_bounds__(256, 1) __cluster_dims__(8, 1, 1)
k_lstm(const float* __restrict__ w_hh, const int* __restrict__ lengths,
       int layer, int out_fp32) {
    __shared__ __align__(16) __nv_bfloat16 h_shD[2][16 * 264]; // dbl-buffered full h
    __shared__ __align__(16) unsigned long long h_own[8][16];  // [warp][batch] 4 units
    __shared__ int len_sh[16];

    int cta = blockIdx.x;
    int ub  = cta & 7;          // cluster rank
    int grp = cta >> 3;
    int bb  = grp & 3;
    int dir = grp >> 2;
    int tid = threadIdx.x;
    int w = tid >> 5, lane = tid & 31;

    // ---- B fragments: warp w's 16 columns = units {4w..4w+3} x gates {0..3} ----
    unsigned bfr[16][2][2];
    {
        int c2 = (lane & 3) * 2;
#pragma unroll
        for (int p = 0; p < 2; ++p) {
            int lc = 8 * p + (lane >> 2);
            int g = lc & 3, du = lc >> 2;
            const float* wr = w_hh +
                ((size_t)((layer * 2 + dir) * 1024 + g * 256 + ub * 32 + w * 4 + du)) * 256;
#pragma unroll
            for (int kt = 0; kt < 16; ++kt) {
                bfr[kt][p][0] = pack_bf2(wr[kt * 16 + c2],     wr[kt * 16 + c2 + 1]);
                bfr[kt][p][1] = pack_bf2(wr[kt * 16 + c2 + 8], wr[kt * 16 + c2 + 9]);
            }
        }
    }
    if (tid < 16) len_sh[tid] = lengths[bb * 16 + tid];
    // zero h_shD[0] (step-0 h state)
    for (int i = tid; i < 16 * 264 / 2; i += 256)
        ((unsigned*)h_shD[0])[i] = 0u;
    __syncthreads();
    asm volatile("barrier.cluster.arrive.aligned;" ::: "memory");
    asm volatile("barrier.cluster.wait.aligned;" ::: "memory");

    int maxlen = 0;
#pragma unroll
    for (int i = 0; i < 16; i++) maxlen = max(maxlen, len_sh[i]);

    // gate mapping: thread (w, lane) -> batches r, r+8 ; unit 4w + du
    int q = lane & 3, r = lane >> 2;
    bool qe = (q & 1) == 0;
    int du = ((q & 1) << 1) | (q >> 1);
    int unit = ub * 32 + 4 * w + du;
    int len0 = len_sh[r], len1 = len_sh[r + 8];
    int gb0 = bb * 16 + r, gb1 = bb * 16 + r + 8;
    const __nv_bfloat16* xg0p = g_xg + (size_t)gb0 * T_ * 2048 + dir * 1024 + unit;
    const __nv_bfloat16* xg1p = g_xg + (size_t)gb1 * T_ * 2048 + dir * 1024 + unit;

    unsigned hsh_base = (unsigned)__cvta_generic_to_shared(&h_shD[0][0]);
    unsigned a_addr0 = hsh_base + (unsigned)(lane & 15) * 528 + ((lane >> 4) << 4);

    // push: lane's FIXED peer = lane&7; batches (lane>>3)+{0,4,8,12}
    int peer = lane & 7;
    unsigned dsm_peer = mapa_u32(hsh_base + (unsigned)((ub * 32 + 4 * w) * 2), peer);

    float cst0 = 0.f, cst1 = 0.f;
    float xa[2][8];

    // prefetch xg for s = 0
    {
        int pos0 = dir ? (len0 - 1) : 0;
        int pos1 = dir ? (len1 - 1) : 0;
        const __nv_bfloat16* p0 = xg0p + (size_t)pos0 * 2048;
        const __nv_bfloat16* p1 = xg1p + (size_t)pos1 * 2048;
        xa[0][0] = __bfloat162float(p0[0]);   xa[0][1] = __bfloat162float(p0[256]);
        xa[0][2] = __bfloat162float(p0[512]); xa[0][3] = __bfloat162float(p0[768]);
        xa[0][4] = __bfloat162float(p1[0]);   xa[0][5] = __bfloat162float(p1[256]);
        xa[0][6] = __bfloat162float(p1[512]); xa[0][7] = __bfloat162float(p1[768]);
    }

    for (int s = 0; s < maxlen; ++s) {
        int p = s & 1;
        // ---- prefetch xg for s+1 (issues before the barrier wait) ----
        if (s + 1 < maxlen) {
            int sn = s + 1;
            if (sn < len0) {
                int pos0 = dir ? (len0 - 1 - sn) : sn;
                const __nv_bfloat16* pp = xg0p + (size_t)pos0 * 2048;
                xa[p ^ 1][0] = __bfloat162float(pp[0]);
                xa[p ^ 1][1] = __bfloat162float(pp[256]);
                xa[p ^ 1][2] = __bfloat162float(pp[512]);
                xa[p ^ 1][3] = __bfloat162float(pp[768]);
            }
            if (sn < len1) {
                int pos1 = dir ? (len1 - 1 - sn) : sn;
                const __nv_bfloat16* pp = xg1p + (size_t)pos1 * 2048;
                xa[p ^ 1][4] = __bfloat162float(pp[0]);
                xa[p ^ 1][5] = __bfloat162float(pp[256]);
                xa[p ^ 1][6] = __bfloat162float(pp[512]);
                xa[p ^ 1][7] = __bfloat162float(pp[768]);
            }
        }

        // ---- wait: peers' pushes from step s-1 into h_shD[p] landed ----
        if (s > 0)
            asm volatile("barrier.cluster.wait.aligned;" ::: "memory");

        // ---- recurrent mma, split even/odd-kt chains ----
        unsigned a_addr = a_addr0 + (unsigned)p * HBUF;
        float aA[2][4], aB[2][4];
#pragma unroll
        for (int t = 0; t < 2; ++t)
#pragma unroll
            for (int i = 0; i < 4; ++i) { aA[t][i] = 0.f; aB[t][i] = 0.f; }
#pragma unroll
        for (int kt = 0; kt < 16; kt += 2) {
            unsigned A0, A1, A2, A3;
            ldsm4(A0, A1, A2, A3, a_addr + kt * 32);
            mma_bf(aA[0][0], aA[0][1], aA[0][2], aA[0][3],
                   A0, A1, A2, A3, bfr[kt][0][0], bfr[kt][0][1]);
            mma_bf(aA[1][0], aA[1][1], aA[1][2], aA[1][3],
                   A0, A1, A2, A3, bfr[kt][1][0], bfr[kt][1][1]);
            unsigned B0, B1, B2, B3;
            ldsm4(B0, B1, B2, B3, a_addr + (kt + 1) * 32);
            mma_bf(aB[0][0], aB[0][1], aB[0][2], aB[0][3],
                   B0, B1, B2, B3, bfr[kt + 1][0][0], bfr[kt + 1][0][1]);
            mma_bf(aB[1][0], aB[1][1], aB[1][2], aB[1][3],
                   B0, B1, B2, B3, bfr[kt + 1][1][0], bfr[kt + 1][1][1]);
        }
        float acc0[4], acc1[4];
#pragma unroll
        for (int i = 0; i < 4; ++i) { acc0[i] = aA[0][i] + aB[0][i];
                                      acc1[i] = aA[1][i] + aB[1][i]; }

        // ---- lane-pair exchange: swap the "other" ntile with partner ----
        float own[4], rcv[4];
#pragma unroll
        for (int i = 0; i < 4; ++i) {
            float snd = qe ? acc1[i] : acc0[i];
            rcv[i] = __shfl_xor_sync(0xFFFFFFFFu, snd, 1);
            own[i] = qe ? acc0[i] : acc1[i];
        }
        float ai0 = (qe ? own[0] : rcv[0]) + xa[p][0];
        float af0 = (qe ? own[1] : rcv[1]) + xa[p][1];
        float ag0 = (qe ? rcv[0] : own[0]) + xa[p][2];
        float ao0 = (qe ? rcv[1] : own[1]) + xa[p][3];
        float ai1 = (qe ? own[2] : rcv[2]) + xa[p][4];
        float af1 = (qe ? own[3] : rcv[3]) + xa[p][5];
        float ag1 = (qe ? rcv[2] : own[2]) + xa[p][6];
        float ao1 = (qe ? rcv[3] : own[3]) + xa[p][7];

        bool v0 = s < len0, v1 = s < len1;
        float hv0 = 0.f, hv1 = 0.f;
        if (v0) {
            cst0 = sigm(af0) * cst0 + sigm(ai0) * tanhfast(ag0);
            hv0 = sigm(ao0) * tanhfast(cst0);
            ((__nv_bfloat16*)&h_own[w][r])[du] = __float2bfloat16(hv0);
        }
        if (v1) {
            cst1 = sigm(af1) * cst1 + sigm(ai1) * tanhfast(ag1);
            hv1 = sigm(ao1) * tanhfast(cst1);
            ((__nv_bfloat16*)&h_own[w][r + 8])[du] = __float2bfloat16(hv1);
        }
        __syncwarp();

        // ---- push own 4-unit slice (all 16 batches) to fixed peer ----
        if (s + 1 < maxlen) {
            unsigned dbase = dsm_peer + (unsigned)(p ^ 1) * HBUF;
#pragma unroll
            for (int j = 0; j < 4; ++j) {
                int batch = (lane >> 3) + 4 * j;
                st_dsm64(dbase + (unsigned)batch * 528, h_own[w][batch]);
            }
            asm volatile("barrier.cluster.arrive.aligned;" ::: "memory");
        }

        // ---- off critical path: write layer output ----
        if (v0) {
            int pos0 = dir ? (len0 - 1 - s) : s;
            size_t xoff = ((size_t)gb0 * T_ + pos0) * E_ + dir * H_ + unit;
            if (out_fp32) g_xA[xoff] = hv0; else g_xbfB[xoff] = __float2bfloat16(hv0);
        }
        if (v1) {
            int pos1 = dir ? (len1 - 1 - s) : s;
            size_t xoff = ((size_t)gb1 * T_ + pos1) * E_ + dir * H_ + unit;
            if (out_fp32) g_xA[xoff] = hv1; else g_xbfB[xoff] = __float2bfloat16(hv1);
        }
    }

    // ---- fused tail zeroing: positions t in [len, T) get zeros ----
    for (int t = len0; t < T_; ++t) {
        size_t xoff = ((size_t)gb0 * T_ + t) * E_ + dir * H_ + unit;
        if (out_fp32) g_xA[xoff] = 0.f; else g_xbfB[xoff] = __float2bfloat16(0.f);
    }
    for (int t = len1; t < T_; ++t) {
        size_t xoff = ((size_t)gb1 * T_ + t) * E_ + dir * H_ + unit;
        if (out_fp32) g_xA[xoff] = 0.f; else g_xbfB[xoff] = __float2bfloat16(0.f);
    }

    // final barrier: cover in-flight remote ops before any CTA exits
    asm volatile("barrier.cluster.arrive.aligned;" ::: "memory");
    asm volatile("barrier.cluster.wait.aligned;" ::: "memory");
}

// ---------------- emissions -----------------------------------------------------
__global__ void k_emis(const float* __restrict__ fc_w, const float* __restrict__ fc_b) {
    int w = blockIdx.x * 8 + (threadIdx.x >> 5);
    int lane = threadIdx.x & 31;
    int j = lane < NT_ ? lane : 0;
    const float* x = g_xA + (size_t)w * E_;
    float acc = fc_b[j];
#pragma unroll 4
    for (int k = 0; k < E_; k += 4) {
        float4 xv = *(const float4*)(x + k);
        acc += xv.x * fc_w[(k + 0) * NT_ + j] + xv.y * fc_w[(k + 1) * NT_ + j]
             + xv.z * fc_w[(k + 2) * NT_ + j] + xv.w * fc_w[(k + 3) * NT_ + j];
    }
    if (lane < NT_) g_em[(size_t)w * NT_ + lane] = acc;
}

// ---------------- CRF -----------------------------------------------------------
__global__ void k_crf(const int* __restrict__ tags, const int* __restrict__ lengths,
                      const float* __restrict__ crf_start, const float* __restrict__ crf_end,
                      const float* __restrict__ crf_trans) {
    int b = blockIdx.x;
    int lane = threadIdx.x;
    int len = lengths[b];
    const int* tg = tags + b * T_;
    const float* em = g_em + (size_t)b * T_ * NT_;

    float part = 0.f;
    for (int t = lane; t < T_; t += 32) {
        if (t < len) {
            int tt = tg[t];
            part += em[t * NT_ + tt];
            if (t >= 1) part += crf_trans[tg[t - 1] * NT_ + tt];
        }
    }
#pragma unroll
    for (int o = 16; o; o >>= 1) part += __shfl_xor_sync(0xFFFFFFFFu, part, o);
    float numer = part + crf_start[tg[0]] + crf_end[tg[len - 1]];

    int j = lane < NT_ ? lane : 0;
    float etr[NT_];
#pragma unroll
    for (int i = 0; i < NT_; i++) etr[i] = expf(crf_trans[i * NT_ + j]);

    float s = crf_start[j] + em[j];
    for (int t = 1; t < len; ++t) {
        float sl = (lane < NT_) ? s : -1e30f;
        float m = sl;
#pragma unroll
        for (int o = 16; o; o >>= 1) m = fmaxf(m, __shfl_xor_sync(0xFFFFFFFFu, m, o));
        float es = expf(s - m);
        float z = 0.f;
#pragma unroll
        for (int i = 0; i < NT_; i++) {
            float ei = __shfl_sync(0xFFFFFFFFu, es, i);
            z += ei * etr[i];
        }
        s = m + logf(z) + em[t * NT_ + j];
    }
    s += crf_end[j];
    float sj = (lane < NT_) ? s : -1e30f;
    float mm = sj;
#pragma unroll
    for (int o = 16; o; o >>= 1) mm = fmaxf(mm, __shfl_xor_sync(0xFFFFFFFFu, mm, o));
    float zz = (lane < NT_) ? expf(sj - mm) : 0.f;
#pragma unroll
    for (int o = 16; o; o >>= 1) zz += __shfl_xor_sync(0xFFFFFFFFu, zz, o);
    float logZ = mm + logf(zz);
    if (lane == 0) g_llh[b] = numer - logZ;
}

// ---------------- final reduction ----------------------------------------------
__global__ void k_reduce(float* __restrict__ out) {
    int lane = threadIdx.x;
    float v = g_llh[lane];
    __shared__ float tmp[2];
#pragma unroll
    for (int o = 16; o; o >>= 1) v += __shfl_xor_sync(0xFFFFFFFFu, v, o);
    if ((lane & 31) == 0) tmp[lane >> 5] = v;
    __syncthreads();
    if (lane == 0) out[0] = -(tmp[0] + tmp[1]);
}

// ---------------- host launcher -------------------------------------------------
extern "C" void kernel_launch(void* const* d_in, const int* in_sizes, int n_in,
                              void* d_out, int out_size) {
    const int*   ids   = (const int*)d_in[0];
    const int*   lens  = (const int*)d_in[1];
    const int*   tags  = (const int*)d_in[2];
    const float* embed = (const float*)d_in[3];
    const float* w_ih  = (const float*)d_in[4];
    const float* w_hh  = (const float*)d_in[5];
    const float* b_ih  = (const float*)d_in[6];
    const float* b_hh  = (const float*)d_in[7];
    const float* fc_w  = (const float*)d_in[8];
    const float* fc_b  = (const float*)d_in[9];
    const float* c_st  = (const float*)d_in[10];
    const float* c_en  = (const float*)d_in[11];
    const float* c_tr  = (const float*)d_in[12];
    float* out = (float*)d_out;

    k_wcvt<<<1024, 256>>>(w_ih, 0);                    // 0
    k_wcvt<<<1024, 256>>>(w_ih, 1);                    // 1
    k_gather<<<B_ * T_, 128>>>(ids, embed);            // 2
    k_gemm_bf<<<dim3(16, 256), 256>>>(b_ih, b_hh, 0);  // 3
    k_lstm<<<64, 256>>>(w_hh, lens, 0, 0);             // 4
    k_gemm_bf<<<dim3(16, 256), 256>>>(b_ih, b_hh, 1);  // 5  <- profiled
    k_lstm<<<64, 256>>>(w_hh, lens, 1, 1);             // 6
    k_emis<<<B_ * T_ / 8, 256>>>(fc_w, fc_b);          // 7
    k_crf<<<B_, 32>>>(tags, lens, c_st, c_en, c_tr);   // 8
    k_reduce<<<1, 64>>>(out);                          // 9
}